// round 5
// baseline (speedup 1.0000x reference)
#include <cuda_runtime.h>
#include <math.h>

#define D 512
#define NBLOCKS 1184
#define BLK 256
#define WARPS_PER_BLK (BLK / 32)
#define EPSN (1e-13f + 1e-14f)

__device__ float g_partial[NBLOCKS];
__device__ unsigned int g_count;  // zero-init; last block wraps it back to 0

__global__ __launch_bounds__(BLK) void rowcos_fused_kernel(const float* __restrict__ s,
                                                           const float* __restrict__ im,
                                                           float* __restrict__ out,
                                                           int N) {
    const int lane = threadIdx.x & 31;
    const int gwarp = (blockIdx.x * BLK + threadIdx.x) >> 5;
    const int nwarps = (gridDim.x * BLK) >> 5;

    float acc = 0.0f;

    // Two rows per warp per iteration: 16 independent LDG.128 in flight
    // (MLP=16) and two interleaved reduction trees to hide SHFL latency.
    int row = gwarp * 2;
    for (; row + 1 < N; row += 2 * nwarps) {
        const float4* sp0 = reinterpret_cast<const float4*>(s + (size_t)row * D);
        const float4* ip0 = reinterpret_cast<const float4*>(im + (size_t)row * D);
        const float4* sp1 = reinterpret_cast<const float4*>(s + (size_t)(row + 1) * D);
        const float4* ip1 = reinterpret_cast<const float4*>(im + (size_t)(row + 1) * D);

        float4 a0[4], b0[4], a1[4], b1[4];
#pragma unroll
        for (int j = 0; j < 4; j++) {
            a0[j] = sp0[lane + j * 32];
            b0[j] = ip0[lane + j * 32];
            a1[j] = sp1[lane + j * 32];
            b1[j] = ip1[lane + j * 32];
        }

        float dot0 = 0.f, ss0 = 0.f, ii0 = 0.f;
        float dot1 = 0.f, ss1 = 0.f, ii1 = 0.f;
#pragma unroll
        for (int j = 0; j < 4; j++) {
            dot0 += a0[j].x * b0[j].x + a0[j].y * b0[j].y + a0[j].z * b0[j].z + a0[j].w * b0[j].w;
            ss0  += a0[j].x * a0[j].x + a0[j].y * a0[j].y + a0[j].z * a0[j].z + a0[j].w * a0[j].w;
            ii0  += b0[j].x * b0[j].x + b0[j].y * b0[j].y + b0[j].z * b0[j].z + b0[j].w * b0[j].w;
            dot1 += a1[j].x * b1[j].x + a1[j].y * b1[j].y + a1[j].z * b1[j].z + a1[j].w * b1[j].w;
            ss1  += a1[j].x * a1[j].x + a1[j].y * a1[j].y + a1[j].z * a1[j].z + a1[j].w * a1[j].w;
            ii1  += b1[j].x * b1[j].x + b1[j].y * b1[j].y + b1[j].z * b1[j].z + b1[j].w * b1[j].w;
        }

        // Six independent butterfly chains — SHFL pipe stays busy.
#pragma unroll
        for (int off = 16; off > 0; off >>= 1) {
            dot0 += __shfl_xor_sync(0xffffffffu, dot0, off);
            ss0  += __shfl_xor_sync(0xffffffffu, ss0,  off);
            ii0  += __shfl_xor_sync(0xffffffffu, ii0,  off);
            dot1 += __shfl_xor_sync(0xffffffffu, dot1, off);
            ss1  += __shfl_xor_sync(0xffffffffu, ss1,  off);
            ii1  += __shfl_xor_sync(0xffffffffu, ii1,  off);
        }

        if (lane == 0) {
            acc -= dot0 / ((sqrtf(ss0) + EPSN) * (sqrtf(ii0) + EPSN));
            acc -= dot1 / ((sqrtf(ss1) + EPSN) * (sqrtf(ii1) + EPSN));
        }
    }
    // Tail (N odd / leftover single row) — N=65536 here so usually unused.
    for (; row < N; row += 2 * nwarps) {
        const float4* sp = reinterpret_cast<const float4*>(s + (size_t)row * D);
        const float4* ip = reinterpret_cast<const float4*>(im + (size_t)row * D);
        float dot = 0.f, ss = 0.f, ii = 0.f;
#pragma unroll
        for (int j = 0; j < 4; j++) {
            float4 a = sp[lane + j * 32];
            float4 b = ip[lane + j * 32];
            dot += a.x * b.x + a.y * b.y + a.z * b.z + a.w * b.w;
            ss  += a.x * a.x + a.y * a.y + a.z * a.z + a.w * a.w;
            ii  += b.x * b.x + b.y * b.y + b.z * b.z + b.w * b.w;
        }
#pragma unroll
        for (int off = 16; off > 0; off >>= 1) {
            dot += __shfl_xor_sync(0xffffffffu, dot, off);
            ss  += __shfl_xor_sync(0xffffffffu, ss,  off);
            ii  += __shfl_xor_sync(0xffffffffu, ii,  off);
        }
        if (lane == 0)
            acc -= dot / ((sqrtf(ss) + EPSN) * (sqrtf(ii) + EPSN));
    }

    __shared__ float wsum[WARPS_PER_BLK];
    if (lane == 0) wsum[threadIdx.x >> 5] = acc;
    __syncthreads();

    __shared__ bool is_last;
    if (threadIdx.x == 0) {
        float bsum = 0.0f;
#pragma unroll
        for (int w = 0; w < WARPS_PER_BLK; w++) bsum += wsum[w];
        g_partial[blockIdx.x] = bsum;
        __threadfence();
        unsigned int done = atomicInc(&g_count, NBLOCKS - 1);  // wraps to 0 at last block
        is_last = (done == NBLOCKS - 1);
    }
    __syncthreads();

    if (is_last) {
        __shared__ float sm[BLK];
        float v = 0.0f;
        for (int i = threadIdx.x; i < NBLOCKS; i += BLK) v += g_partial[i];
        sm[threadIdx.x] = v;
        __syncthreads();
#pragma unroll
        for (int step = BLK / 2; step > 0; step >>= 1) {
            if (threadIdx.x < step) sm[threadIdx.x] += sm[threadIdx.x + step];
            __syncthreads();
        }
        if (threadIdx.x == 0) out[0] = sm[0];
    }
}

extern "C" void kernel_launch(void* const* d_in, const int* in_sizes, int n_in,
                              void* d_out, int out_size) {
    const float* s  = (const float*)d_in[0];
    const float* im = (const float*)d_in[1];
    const int N = in_sizes[0] / D;

    rowcos_fused_kernel<<<NBLOCKS, BLK>>>(s, im, (float*)d_out, N);
}

// round 6
// speedup vs baseline: 1.0620x; 1.0620x over previous
#include <cuda_runtime.h>
#include <math.h>

#define D 512
#define NBLOCKS 1184
#define BLK 256
#define WARPS_PER_BLK (BLK / 32)
#define EPSN (1e-13f + 1e-14f)

__device__ float g_partial[NBLOCKS];
__device__ unsigned int g_count;  // zero-init; last block wraps it back to 0

__global__ __launch_bounds__(BLK) void rowcos_fused_kernel(const float* __restrict__ s,
                                                           const float* __restrict__ im,
                                                           float* __restrict__ out,
                                                           int N) {
    const int lane = threadIdx.x & 31;
    const int g    = lane >> 3;   // group 0..3 -> row offset within the warp's 4 rows
    const int l8   = lane & 7;    // lane within 8-lane group
    const int gwarp = (blockIdx.x * BLK + threadIdx.x) >> 5;
    const int nwarps = (gridDim.x * BLK) >> 5;

    float acc = 0.0f;

    // 4 rows per warp: each 8-lane group owns one row (128 float4 per array,
    // 16 float4 per lane, in 4 chunks of 4). One SHFL instruction reduces all
    // 4 groups at once; butterfly depth is 3 instead of 5.
    int row_base = gwarp * 4;
    for (; row_base + 3 < N; row_base += 4 * nwarps) {
        const int r = row_base + g;
        const float4* sp = reinterpret_cast<const float4*>(s + (size_t)r * D);
        const float4* ip = reinterpret_cast<const float4*>(im + (size_t)r * D);

        float dot = 0.f, ss = 0.f, ii = 0.f;
#pragma unroll
        for (int c = 0; c < 4; c++) {
            float4 a[4], b[4];
#pragma unroll
            for (int j = 0; j < 4; j++) {
                a[j] = sp[l8 + (c * 4 + j) * 8];
                b[j] = ip[l8 + (c * 4 + j) * 8];
            }
#pragma unroll
            for (int j = 0; j < 4; j++) {
                dot += a[j].x * b[j].x + a[j].y * b[j].y + a[j].z * b[j].z + a[j].w * b[j].w;
                ss  += a[j].x * a[j].x + a[j].y * a[j].y + a[j].z * a[j].z + a[j].w * a[j].w;
                ii  += b[j].x * b[j].x + b[j].y * b[j].y + b[j].z * b[j].z + b[j].w * b[j].w;
            }
        }

        // 3-level butterfly within each 8-lane group (groups are lane-aligned,
        // so xor offsets 4,2,1 stay inside the group).
#pragma unroll
        for (int off = 4; off > 0; off >>= 1) {
            dot += __shfl_xor_sync(0xffffffffu, dot, off);
            ss  += __shfl_xor_sync(0xffffffffu, ss,  off);
            ii  += __shfl_xor_sync(0xffffffffu, ii,  off);
        }

        if (l8 == 0) {
            acc -= dot / ((sqrtf(ss) + EPSN) * (sqrtf(ii) + EPSN));
        }
    }

    // Tail: up to 3 leftover rows; group g handles row_base+g if valid.
    {
        const int r = row_base + g;
        if (r < N) {
            const float4* sp = reinterpret_cast<const float4*>(s + (size_t)r * D);
            const float4* ip = reinterpret_cast<const float4*>(im + (size_t)r * D);
            float dot = 0.f, ss = 0.f, ii = 0.f;
#pragma unroll
            for (int c = 0; c < 4; c++) {
#pragma unroll
                for (int j = 0; j < 4; j++) {
                    float4 a = sp[l8 + (c * 4 + j) * 8];
                    float4 b = ip[l8 + (c * 4 + j) * 8];
                    dot += a.x * b.x + a.y * b.y + a.z * b.z + a.w * b.w;
                    ss  += a.x * a.x + a.y * a.y + a.z * a.z + a.w * a.w;
                    ii  += b.x * b.x + b.y * b.y + b.z * b.z + b.w * b.w;
                }
            }
#pragma unroll
            for (int off = 4; off > 0; off >>= 1) {
                dot += __shfl_xor_sync(0xffffffffu, dot, off);
                ss  += __shfl_xor_sync(0xffffffffu, ss,  off);
                ii  += __shfl_xor_sync(0xffffffffu, ii,  off);
            }
            if (l8 == 0) {
                acc -= dot / ((sqrtf(ss) + EPSN) * (sqrtf(ii) + EPSN));
            }
        }
        __syncwarp();
    }

    // Fold the 4 group-leader partials (other lanes hold 0) across the warp.
#pragma unroll
    for (int off = 16; off > 0; off >>= 1)
        acc += __shfl_xor_sync(0xffffffffu, acc, off);

    __shared__ float wsum[WARPS_PER_BLK];
    if (lane == 0) wsum[threadIdx.x >> 5] = acc;
    __syncthreads();

    __shared__ bool is_last;
    if (threadIdx.x == 0) {
        float bsum = 0.0f;
#pragma unroll
        for (int w = 0; w < WARPS_PER_BLK; w++) bsum += wsum[w];
        g_partial[blockIdx.x] = bsum;
        __threadfence();
        unsigned int done = atomicInc(&g_count, NBLOCKS - 1);  // wraps to 0 at last block
        is_last = (done == NBLOCKS - 1);
    }
    __syncthreads();

    if (is_last) {
        __shared__ float sm[BLK];
        float v = 0.0f;
        for (int i = threadIdx.x; i < NBLOCKS; i += BLK) v += g_partial[i];
        sm[threadIdx.x] = v;
        __syncthreads();
#pragma unroll
        for (int step = BLK / 2; step > 0; step >>= 1) {
            if (threadIdx.x < step) sm[threadIdx.x] += sm[threadIdx.x + step];
            __syncthreads();
        }
        if (threadIdx.x == 0) out[0] = sm[0];
    }
}

extern "C" void kernel_launch(void* const* d_in, const int* in_sizes, int n_in,
                              void* d_out, int out_size) {
    const float* s  = (const float*)d_in[0];
    const float* im = (const float*)d_in[1];
    const int N = in_sizes[0] / D;

    rowcos_fused_kernel<<<NBLOCKS, BLK>>>(s, im, (float*)d_out, N);
}